// round 13
// baseline (speedup 1.0000x reference)
#include <cuda_runtime.h>

// Soft quantizer forward == hard nearest-level quantization (see R1 notes).
// R9: L2 pinning, fixed for sm_103 — evict_last demands 256-bit loads, so use
// ld.global.nc.L2::evict_last.v8.b32 (32B/load). Input (67MB) pinned
// evict-last in 126MB L2 across graph replays; stores st.global.cs
// (evict-first) so the write stream can't displace it.

__device__ __forceinline__ float quant1(float x) {
    const float INV_STEP = 12.0f;
    const float STEP     = 2.0f / 24.0f;
    float k = rintf(fmaf(x, INV_STEP, INV_STEP));
    k = fminf(fmaxf(k, 0.0f), 24.0f);
    return fmaf(k, STEP, -1.0f);
}

struct F8 { float v[8]; };

// 256-bit load with L2 evict_last residency hint.
__device__ __forceinline__ F8 ld8_evict_last(const void* p) {
    F8 r;
    asm volatile("ld.global.nc.L2::evict_last.v8.b32 "
                 "{%0,%1,%2,%3,%4,%5,%6,%7}, [%8];"
                 : "=f"(r.v[0]), "=f"(r.v[1]), "=f"(r.v[2]), "=f"(r.v[3]),
                   "=f"(r.v[4]), "=f"(r.v[5]), "=f"(r.v[6]), "=f"(r.v[7])
                 : "l"(p));
    return r;
}

// 128-bit streaming (evict-first) store.
__device__ __forceinline__ void st4_streaming(void* p, float a, float b, float c, float d) {
    asm volatile("st.global.cs.v4.f32 [%0], {%1,%2,%3,%4};"
                 :: "l"(p), "f"(a), "f"(b), "f"(c), "f"(d)
                 : "memory");
}

#define TPB 256
#define VEC 2   // 32B chunks per thread

// Exact-cover: grid * TPB * VEC == n8 (32B units), no guards.
__global__ void __launch_bounds__(TPB) quant_kernel_r9(const float* __restrict__ in,
                                                       float* __restrict__ out) {
    long base = (long)blockIdx.x * (TPB * VEC) + threadIdx.x;  // in 32B units

    F8 d[VEC];
#pragma unroll
    for (int j = 0; j < VEC; j++)
        d[j] = ld8_evict_last(in + (base + j * TPB) * 8);

#pragma unroll
    for (int j = 0; j < VEC; j++) {
        float q[8];
#pragma unroll
        for (int e = 0; e < 8; e++) q[e] = quant1(d[j].v[e]);
        float* p = out + (base + j * TPB) * 8;
        st4_streaming(p,     q[0], q[1], q[2], q[3]);
        st4_streaming(p + 4, q[4], q[5], q[6], q[7]);
    }
}

// Guarded scalar fallback for any remainder (not hit for this shape).
__global__ void quant_tail(const float* __restrict__ in, float* __restrict__ out,
                           int start, int n) {
    int i = start + blockIdx.x * blockDim.x + threadIdx.x;
    if (i < n) out[i] = quant1(in[i]);
}

extern "C" void kernel_launch(void* const* d_in, const int* in_sizes, int n_in,
                              void* d_out, int out_size) {
    const float* x = (const float*)d_in[0];
    float* out = (float*)d_out;
    int n = out_size;

    int n8 = n / 8;                       // 32B chunks
    const int per_block = TPB * VEC;
    int full_blocks = n8 / per_block;
    if (full_blocks > 0) {
        quant_kernel_r9<<<full_blocks, TPB>>>(x, out);
    }
    int done = full_blocks * per_block * 8;
    if (done < n) {
        int rem = n - done;
        quant_tail<<<(rem + TPB - 1) / TPB, TPB>>>(x, out, done, n);
    }
}

// round 14
// speedup vs baseline: 1.1011x; 1.1011x over previous
#include <cuda_runtime.h>

// Soft quantizer forward == hard nearest-level quantization (see R1 notes).
// R13: consolidation of best-known config (R3: VEC=4, streaming stores) with
//  - guard-free exact cover (no predicates in hot kernel)
//  - __ldcg loads (L2-only; no L1 allocate — data has zero L1 reuse)
//  - __stcs stores (evict-first; write stream can't displace L2-resident input)
//  - two-phase load/store interleave to keep read+write DRAM streams concurrent.

__device__ __forceinline__ float quant1(float x) {
    const float INV_STEP = 12.0f;
    const float STEP     = 2.0f / 24.0f;
    float k = rintf(fmaf(x, INV_STEP, INV_STEP));
    k = fminf(fmaxf(k, 0.0f), 24.0f);
    return fmaf(k, STEP, -1.0f);
}

__device__ __forceinline__ float4 quant4(float4 v) {
    float4 r;
    r.x = quant1(v.x);
    r.y = quant1(v.y);
    r.z = quant1(v.z);
    r.w = quant1(v.w);
    return r;
}

#define TPB 256
#define VEC 4

// Exact cover: grid * TPB * VEC == n4. No guards.
__global__ void __launch_bounds__(TPB) quant_kernel_r13(const float4* __restrict__ in,
                                                        float4* __restrict__ out) {
    int base = blockIdx.x * (TPB * VEC) + threadIdx.x;

    // Phase 1: two independent loads, quantize, stream out.
    float4 a0 = __ldcg(&in[base]);
    float4 a1 = __ldcg(&in[base + TPB]);
    // Phase 2 loads issued before phase-1 stores so reads stay ahead.
    float4 b0 = __ldcg(&in[base + 2 * TPB]);
    float4 b1 = __ldcg(&in[base + 3 * TPB]);

    __stcs(&out[base],       quant4(a0));
    __stcs(&out[base + TPB], quant4(a1));
    __stcs(&out[base + 2 * TPB], quant4(b0));
    __stcs(&out[base + 3 * TPB], quant4(b1));
}

// Guarded fallback for non-divisible shapes (not hit for this shape).
__global__ void __launch_bounds__(TPB) quant_kernel_g(const float4* __restrict__ in,
                                                      float4* __restrict__ out,
                                                      int n4, int start4) {
    int i = start4 + blockIdx.x * TPB + threadIdx.x;
    if (i < n4) __stcs(&out[i], quant4(__ldcg(&in[i])));
}

__global__ void quant_tail(const float* __restrict__ in, float* __restrict__ out,
                           int start, int n) {
    int i = start + blockIdx.x * blockDim.x + threadIdx.x;
    if (i < n) out[i] = quant1(in[i]);
}

extern "C" void kernel_launch(void* const* d_in, const int* in_sizes, int n_in,
                              void* d_out, int out_size) {
    const float* x = (const float*)d_in[0];
    float* out = (float*)d_out;
    int n = out_size;
    int n4 = n / 4;

    const int per_block = TPB * VEC;
    int full_blocks = n4 / per_block;
    if (full_blocks > 0) {
        quant_kernel_r13<<<full_blocks, TPB>>>((const float4*)x, (float4*)out);
    }
    int done4 = full_blocks * per_block;
    int rem4 = n4 - done4;
    if (rem4 > 0) {
        quant_kernel_g<<<(rem4 + TPB - 1) / TPB, TPB>>>((const float4*)x, (float4*)out,
                                                        n4, done4);
    }
    int rem = n - n4 * 4;
    if (rem > 0) {
        quant_tail<<<1, 32>>>(x, out, n4 * 4, n);
    }
}